// round 1
// baseline (speedup 1.0000x reference)
#include <cuda_runtime.h>
#include <cuda_bf16.h>
#include <cstddef>

// Problem constants
// B=2, S=2048, DIM=1024, HQ=16, HKV=4, HD=64, M = B*S = 4096
#define M_ROWS 4096
#define SEQ    2048
#define KDIM   1024

// Scratch (device globals; no allocation allowed)
__device__ float g_q[4096 * 1024];   // [B*S, HQ*64]  (RoPE'd, pre-scaled by 0.125)
__device__ float g_k[4096 * 256];    // [B*S, HKV*64] (RoPE'd)
__device__ float g_v[4096 * 256];    // [B*S, HKV*64]
__device__ float g_attn[4096 * 1024];// [B*S, HQ*64]

// ---------------------------------------------------------------------------
// 128x128x8 register-blocked fp32 GEMM: C[M,N] = A[M,K] @ W[K,N], K=1024 fixed.
// RMODE: 0 = plain, 1 = RoPE epilogue (K proj), 2 = RoPE + 0.125 scale (Q proj)
// M multiple of 128, N multiple of 128 (N in {256,1024}).
// ---------------------------------------------------------------------------
template <int RMODE>
__global__ void __launch_bounds__(256) sgemm_rope(
    const float* __restrict__ A, const float* __restrict__ W,
    float* __restrict__ C, int N,
    const float* __restrict__ fc, const float* __restrict__ fs)
{
    __shared__ float As[8][128];
    __shared__ float Bs[8][128];

    const int tid  = threadIdx.x;
    const int tx   = tid & 15;
    const int ty   = tid >> 4;
    const int brow = blockIdx.y * 128;
    const int bcol = blockIdx.x * 128;

    // A tile loader: 128 rows x 8 cols; one float4 per thread
    const int arow = tid >> 1;
    const int acol = (tid & 1) << 2;
    // B tile loader: 8 rows x 128 cols; one float4 per thread
    const int brw  = tid >> 5;
    const int bcl  = (tid & 31) << 2;

    const float* Ap = A + (size_t)(brow + arow) * KDIM + acol;
    const float* Bp = W + (size_t)brw * N + bcol + bcl;

    float acc[8][8];
    #pragma unroll
    for (int i = 0; i < 8; ++i)
        #pragma unroll
        for (int j = 0; j < 8; ++j) acc[i][j] = 0.f;

    for (int kt = 0; kt < KDIM; kt += 8) {
        float4 av = *reinterpret_cast<const float4*>(Ap + kt);
        As[acol + 0][arow] = av.x;
        As[acol + 1][arow] = av.y;
        As[acol + 2][arow] = av.z;
        As[acol + 3][arow] = av.w;
        float4 bv = *reinterpret_cast<const float4*>(Bp + (size_t)kt * N);
        *reinterpret_cast<float4*>(&Bs[brw][bcl]) = bv;
        __syncthreads();

        #pragma unroll
        for (int k = 0; k < 8; ++k) {
            float a[8], b[8];
            #pragma unroll
            for (int i = 0; i < 8; ++i) a[i] = As[k][ty * 8 + i];
            #pragma unroll
            for (int j = 0; j < 8; ++j) b[j] = Bs[k][tx * 8 + j];
            #pragma unroll
            for (int i = 0; i < 8; ++i)
                #pragma unroll
                for (int j = 0; j < 8; ++j)
                    acc[i][j] = fmaf(a[i], b[j], acc[i][j]);
        }
        __syncthreads();
    }

    const int cbase = bcol + tx * 8;
    #pragma unroll
    for (int i = 0; i < 8; ++i) {
        const int r = brow + ty * 8 + i;
        float* crow = C + (size_t)r * N + cbase;
        if (RMODE > 0) {
            const int srow = r & (SEQ - 1);
            #pragma unroll
            for (int j = 0; j < 8; j += 2) {
                const int pair = ((cbase + j) & 63) >> 1;
                const float c  = fc[srow * 32 + pair];
                const float s  = fs[srow * 32 + pair];
                const float xr = acc[i][j];
                const float xi = acc[i][j + 1];
                float orv = xr * c - xi * s;
                float oiv = xr * s + xi * c;
                if (RMODE == 2) { orv *= 0.125f; oiv *= 0.125f; }
                acc[i][j]     = orv;
                acc[i][j + 1] = oiv;
            }
        }
        *reinterpret_cast<float4*>(crow)     = make_float4(acc[i][0], acc[i][1], acc[i][2], acc[i][3]);
        *reinterpret_cast<float4*>(crow + 4) = make_float4(acc[i][4], acc[i][5], acc[i][6], acc[i][7]);
    }
}

// ---------------------------------------------------------------------------
// Flash attention (causal, GQA 16q/4kv, head_dim 64, fp32).
// One thread = one query row. Block = 128 queries of one (b,h).
// Q is pre-scaled by 1/sqrt(64). Online softmax with lazy rescale.
// ---------------------------------------------------------------------------
__global__ void __launch_bounds__(128) attn_kernel(
    const float* __restrict__ Q, const float* __restrict__ Kg,
    const float* __restrict__ Vg, float* __restrict__ O)
{
    const int b  = blockIdx.z;
    const int h  = blockIdx.y;
    const int qt = blockIdx.x;
    const int t  = threadIdx.x;
    const int qi = qt * 128 + t;      // query position in sequence
    const int hk = h >> 2;            // GQA kv head

    __shared__ float4 ks[64][16];
    __shared__ float4 vs[64][16];

    float4 qreg[16];
    const float4* qp =
        reinterpret_cast<const float4*>(Q + ((size_t)(b * SEQ + qi) * 16 + h) * 64);
    #pragma unroll
    for (int i = 0; i < 16; ++i) qreg[i] = qp[i];

    float4 acc[16];
    #pragma unroll
    for (int i = 0; i < 16; ++i) acc[i] = make_float4(0.f, 0.f, 0.f, 0.f);
    float m = -1e30f, l = 0.f;

    const int ntiles = qt * 2 + 2;   // key tiles of 64 covering causal range of block
    for (int kt = 0; kt < ntiles; ++kt) {
        const float4* kbase = reinterpret_cast<const float4*>(
            Kg + ((size_t)(b * SEQ + kt * 64) * 4 + hk) * 64);
        const float4* vbase = reinterpret_cast<const float4*>(
            Vg + ((size_t)(b * SEQ + kt * 64) * 4 + hk) * 64);
        // row stride between consecutive keys = 256 floats = 64 float4
        #pragma unroll
        for (int it = 0; it < 8; ++it) {
            const int idx = t + it * 128;
            const int j   = idx >> 4;
            const int d4  = idx & 15;
            ks[j][d4] = kbase[(size_t)j * 64 + d4];
            vs[j][d4] = vbase[(size_t)j * 64 + d4];
        }
        __syncthreads();

        int jmax = qi - kt * 64 + 1;
        if (jmax > 64) jmax = 64;
        for (int j = 0; j < jmax; ++j) {
            float s0 = 0.f, s1 = 0.f, s2 = 0.f, s3 = 0.f;
            #pragma unroll
            for (int i = 0; i < 16; i += 4) {
                const float4 k0 = ks[j][i + 0];
                const float4 k1 = ks[j][i + 1];
                const float4 k2 = ks[j][i + 2];
                const float4 k3 = ks[j][i + 3];
                s0 += qreg[i + 0].x * k0.x + qreg[i + 0].y * k0.y +
                      qreg[i + 0].z * k0.z + qreg[i + 0].w * k0.w;
                s1 += qreg[i + 1].x * k1.x + qreg[i + 1].y * k1.y +
                      qreg[i + 1].z * k1.z + qreg[i + 1].w * k1.w;
                s2 += qreg[i + 2].x * k2.x + qreg[i + 2].y * k2.y +
                      qreg[i + 2].z * k2.z + qreg[i + 2].w * k2.w;
                s3 += qreg[i + 3].x * k3.x + qreg[i + 3].y * k3.y +
                      qreg[i + 3].z * k3.z + qreg[i + 3].w * k3.w;
            }
            const float sc = (s0 + s1) + (s2 + s3);

            if (sc > m) {                       // lazy rescale (rare)
                const float alpha = __expf(m - sc);
                m = sc;
                l *= alpha;
                #pragma unroll
                for (int i = 0; i < 16; ++i) {
                    acc[i].x *= alpha; acc[i].y *= alpha;
                    acc[i].z *= alpha; acc[i].w *= alpha;
                }
            }
            const float p = __expf(sc - m);
            l += p;
            #pragma unroll
            for (int i = 0; i < 16; ++i) {
                const float4 vv = vs[j][i];
                acc[i].x = fmaf(p, vv.x, acc[i].x);
                acc[i].y = fmaf(p, vv.y, acc[i].y);
                acc[i].z = fmaf(p, vv.z, acc[i].z);
                acc[i].w = fmaf(p, vv.w, acc[i].w);
            }
        }
        __syncthreads();
    }

    const float inv = 1.0f / l;
    float4* op = reinterpret_cast<float4*>(O + ((size_t)(b * SEQ + qi) * 16 + h) * 64);
    #pragma unroll
    for (int i = 0; i < 16; ++i)
        op[i] = make_float4(acc[i].x * inv, acc[i].y * inv, acc[i].z * inv, acc[i].w * inv);
}

// ---------------------------------------------------------------------------
// Launch: QKV proj (+RoPE fused) -> flash attention -> output proj
// Inputs: x, start_pos, freqs_cos, freqs_sin, mask, wq, wk, wv, wo
// start_pos = 0 and mask is exactly causal tril(-1e9) -> handled analytically.
// ---------------------------------------------------------------------------
extern "C" void kernel_launch(void* const* d_in, const int* in_sizes, int n_in,
                              void* d_out, int out_size)
{
    const float* x  = (const float*)d_in[0];
    const float* fc = (const float*)d_in[2];
    const float* fs = (const float*)d_in[3];
    const float* wq = (const float*)d_in[5];
    const float* wk = (const float*)d_in[6];
    const float* wv = (const float*)d_in[7];
    const float* wo = (const float*)d_in[8];
    float* out = (float*)d_out;

    float *gq, *gk, *gv, *ga;
    cudaGetSymbolAddress((void**)&gq, g_q);
    cudaGetSymbolAddress((void**)&gk, g_k);
    cudaGetSymbolAddress((void**)&gv, g_v);
    cudaGetSymbolAddress((void**)&ga, g_attn);

    // Q projection + RoPE + 1/sqrt(d) scale : [4096,1024] @ [1024,1024]
    sgemm_rope<2><<<dim3(8, 32), 256>>>(x, wq, gq, 1024, fc, fs);
    // K projection + RoPE : [4096,1024] @ [1024,256]
    sgemm_rope<1><<<dim3(2, 32), 256>>>(x, wk, gk, 256, fc, fs);
    // V projection : [4096,1024] @ [1024,256]
    sgemm_rope<0><<<dim3(2, 32), 256>>>(x, wv, gv, 256, nullptr, nullptr);
    // Flash attention: grid (qtiles=16, heads=16, batch=2)
    attn_kernel<<<dim3(16, 16, 2), 128>>>(gq, gk, gv, ga);
    // Output projection: [4096,1024] @ [1024,1024] -> d_out
    sgemm_rope<0><<<dim3(8, 32), 256>>>(ga, wo, out, 1024, nullptr, nullptr);
}

// round 2
// speedup vs baseline: 1.2711x; 1.2711x over previous
#include <cuda_runtime.h>
#include <cuda_bf16.h>
#include <cstddef>

#define SEQ    2048
#define KDIM   1024

// Scratch (device globals; no allocation allowed)
__device__ float g_q[4096 * 1024];   // [B*S, HQ*64]  (RoPE'd, pre-scaled by 0.125)
__device__ float g_k[4096 * 256];    // [B*S, HKV*64] (RoPE'd)
__device__ float g_v[4096 * 256];    // [B*S, HKV*64]
__device__ float g_attn[4096 * 1024];// [B*S, HQ*64]

// ---------------------------------------------------------------------------
// Packed f32x2 helpers (sm_103a FFMA2 path — PTX only, ptxas won't auto-fuse)
// ---------------------------------------------------------------------------
__device__ __forceinline__ float2 ffma2(float2 a, float2 b, float2 c) {
    unsigned long long au = *reinterpret_cast<unsigned long long*>(&a);
    unsigned long long bu = *reinterpret_cast<unsigned long long*>(&b);
    unsigned long long cu = *reinterpret_cast<unsigned long long*>(&c);
    unsigned long long du;
    asm("fma.rn.f32x2 %0, %1, %2, %3;" : "=l"(du) : "l"(au), "l"(bu), "l"(cu));
    return *reinterpret_cast<float2*>(&du);
}
__device__ __forceinline__ float2 fmul2(float2 a, float2 b) {
    unsigned long long au = *reinterpret_cast<unsigned long long*>(&a);
    unsigned long long bu = *reinterpret_cast<unsigned long long*>(&b);
    unsigned long long du;
    asm("mul.rn.f32x2 %0, %1, %2;" : "=l"(du) : "l"(au), "l"(bu));
    return *reinterpret_cast<float2*>(&du);
}

// ---------------------------------------------------------------------------
// 128x128x8 register-blocked fp32 GEMM core with packed FMA.
// rmode: 0 = plain, 1 = RoPE (K proj), 2 = RoPE + 0.125 scale (Q proj)
// ---------------------------------------------------------------------------
__device__ __forceinline__ void gemm_core(
    const float* __restrict__ A, const float* __restrict__ W,
    float* __restrict__ C, int N, int brow, int bcol, int rmode,
    const float* __restrict__ fc, const float* __restrict__ fs)
{
    __shared__ float As[8][128];
    __shared__ float Bs[8][128];

    const int tid  = threadIdx.x;
    const int tx   = tid & 15;
    const int ty   = tid >> 4;

    const int arow = tid >> 1;
    const int acol = (tid & 1) << 2;
    const int brw  = tid >> 5;
    const int bcl  = (tid & 31) << 2;

    const float* Ap = A + (size_t)(brow + arow) * KDIM + acol;
    const float* Bp = W + (size_t)brw * N + bcol + bcl;

    float2 acc[8][4];
    #pragma unroll
    for (int i = 0; i < 8; ++i)
        #pragma unroll
        for (int j = 0; j < 4; ++j) acc[i][j] = make_float2(0.f, 0.f);

    for (int kt = 0; kt < KDIM; kt += 8) {
        float4 av = *reinterpret_cast<const float4*>(Ap + kt);
        As[acol + 0][arow] = av.x;
        As[acol + 1][arow] = av.y;
        As[acol + 2][arow] = av.z;
        As[acol + 3][arow] = av.w;
        float4 bv = *reinterpret_cast<const float4*>(Bp + (size_t)kt * N);
        *reinterpret_cast<float4*>(&Bs[brw][bcl]) = bv;
        __syncthreads();

        #pragma unroll
        for (int k = 0; k < 8; ++k) {
            float4 a0 = *reinterpret_cast<const float4*>(&As[k][ty * 8]);
            float4 a1 = *reinterpret_cast<const float4*>(&As[k][ty * 8 + 4]);
            float4 b0 = *reinterpret_cast<const float4*>(&Bs[k][tx * 8]);
            float4 b1 = *reinterpret_cast<const float4*>(&Bs[k][tx * 8 + 4]);
            float2 b2[4];
            b2[0] = make_float2(b0.x, b0.y); b2[1] = make_float2(b0.z, b0.w);
            b2[2] = make_float2(b1.x, b1.y); b2[3] = make_float2(b1.z, b1.w);
            float av8[8] = {a0.x, a0.y, a0.z, a0.w, a1.x, a1.y, a1.z, a1.w};
            #pragma unroll
            for (int i = 0; i < 8; ++i) {
                float2 ad = make_float2(av8[i], av8[i]);
                #pragma unroll
                for (int jj = 0; jj < 4; ++jj)
                    acc[i][jj] = ffma2(ad, b2[jj], acc[i][jj]);
            }
        }
        __syncthreads();
    }

    const int cb = bcol + tx * 8;
    #pragma unroll
    for (int i = 0; i < 8; ++i) {
        const int r = brow + ty * 8 + i;
        float vout[8];
        if (rmode > 0) {
            const int srow = r & (SEQ - 1);
            #pragma unroll
            for (int jj = 0; jj < 4; ++jj) {
                const int pair = ((cb + jj * 2) & 63) >> 1;
                const float c  = fc[srow * 32 + pair];
                const float s  = fs[srow * 32 + pair];
                const float xr = acc[i][jj].x;
                const float xi = acc[i][jj].y;
                float orv = xr * c - xi * s;
                float oiv = xr * s + xi * c;
                if (rmode == 2) { orv *= 0.125f; oiv *= 0.125f; }
                vout[jj * 2]     = orv;
                vout[jj * 2 + 1] = oiv;
            }
        } else {
            #pragma unroll
            for (int jj = 0; jj < 4; ++jj) {
                vout[jj * 2]     = acc[i][jj].x;
                vout[jj * 2 + 1] = acc[i][jj].y;
            }
        }
        float* crow = C + (size_t)r * N + cb;
        *reinterpret_cast<float4*>(crow)     = make_float4(vout[0], vout[1], vout[2], vout[3]);
        *reinterpret_cast<float4*>(crow + 4) = make_float4(vout[4], vout[5], vout[6], vout[7]);
    }
}

// Fused QKV projection: block cols 0-7 -> Q(+RoPE+scale), 8-9 -> K(+RoPE), 10-11 -> V
__global__ void __launch_bounds__(256) qkv_kernel(
    const float* __restrict__ x,
    const float* __restrict__ wq, const float* __restrict__ wk, const float* __restrict__ wv,
    float* __restrict__ gq, float* __restrict__ gk, float* __restrict__ gv,
    const float* __restrict__ fc, const float* __restrict__ fs)
{
    const int bx   = blockIdx.x;
    const int brow = blockIdx.y * 128;
    if (bx < 8)       gemm_core(x, wq, gq, 1024, brow, bx * 128, 2, fc, fs);
    else if (bx < 10) gemm_core(x, wk, gk, 256,  brow, (bx - 8) * 128, 1, fc, fs);
    else              gemm_core(x, wv, gv, 256,  brow, (bx - 10) * 128, 0, nullptr, nullptr);
}

__global__ void __launch_bounds__(256) oproj_kernel(
    const float* __restrict__ A, const float* __restrict__ W, float* __restrict__ C)
{
    gemm_core(A, W, C, 1024, blockIdx.y * 128, blockIdx.x * 128, 0, nullptr, nullptr);
}

// ---------------------------------------------------------------------------
// Flash attention (causal, GQA 16q/4kv, head_dim 64, fp32, packed FMA).
// 2 threads per query: each owns 32 dims; shfl_xor(1) combines QK partials.
// Block = 256 threads = 128 queries of one (b,h). Q pre-scaled by 1/8.
// ---------------------------------------------------------------------------
__global__ void __launch_bounds__(256, 2) attn_kernel(
    const float* __restrict__ Q, const float* __restrict__ Kg,
    const float* __restrict__ Vg, float* __restrict__ O)
{
    const int b    = blockIdx.z;
    const int h    = blockIdx.y;
    const int qt   = (int)gridDim.x - 1 - blockIdx.x;   // heavy tiles first
    const int t    = threadIdx.x;
    const int ql   = t >> 1;
    const int half = t & 1;
    const int qi   = qt * 128 + ql;
    const int hk   = h >> 2;

    __shared__ float4 ks[64][16];   // interleaved: [j][(d&7)*2 + (d>>3)]
    __shared__ float4 vs[64][16];

    float2 q2[16];
    {
        const float4* qp4 = reinterpret_cast<const float4*>(
            Q + ((size_t)(b * SEQ + qi) * 16 + h) * 64 + half * 32);
        #pragma unroll
        for (int i = 0; i < 8; ++i) {
            float4 v = qp4[i];
            q2[2 * i]     = make_float2(v.x, v.y);
            q2[2 * i + 1] = make_float2(v.z, v.w);
        }
    }

    float2 acc2[16];
    #pragma unroll
    for (int i = 0; i < 16; ++i) acc2[i] = make_float2(0.f, 0.f);
    float m = -1e30f, l = 0.f;

    const int wtop = ((t >> 5) << 4) + 15;      // warp's top local query
    const int qtop = qt * 128 + wtop;

    const int ntiles = qt * 2 + 2;
    for (int kt = 0; kt < ntiles; ++kt) {
        const float4* kbase = reinterpret_cast<const float4*>(
            Kg + ((size_t)(b * SEQ + kt * 64) * 4 + hk) * 64);
        const float4* vbase = reinterpret_cast<const float4*>(
            Vg + ((size_t)(b * SEQ + kt * 64) * 4 + hk) * 64);
        #pragma unroll
        for (int it = 0; it < 4; ++it) {
            const int idx = t + it * 256;
            const int j   = idx >> 4;
            const int d   = idx & 15;
            const int ds  = ((d & 7) << 1) | (d >> 3);
            ks[j][ds] = kbase[(size_t)j * 64 + d];
            vs[j][ds] = vbase[(size_t)j * 64 + d];
        }
        __syncthreads();

        int jw = qtop - kt * 64 + 1;            // warp-uniform trip count
        if (jw > 64) jw = 64;
        const int jmine = qi - kt * 64;         // per-thread causal bound

        for (int j = 0; j < jw; ++j) {
            float2 s2 = make_float2(0.f, 0.f);
            #pragma unroll
            for (int i = 0; i < 8; ++i) {
                const float4 kv = ks[j][i * 2 + half];
                s2 = ffma2(q2[2 * i],     make_float2(kv.x, kv.y), s2);
                s2 = ffma2(q2[2 * i + 1], make_float2(kv.z, kv.w), s2);
            }
            float s = s2.x + s2.y;
            s += __shfl_xor_sync(0xffffffffu, s, 1);

            const bool valid = (j <= jmine);
            if (valid && s > m) {               // lazy rescale (rare)
                const float alpha = __expf(m - s);
                m = s;
                l *= alpha;
                const float2 a2 = make_float2(alpha, alpha);
                #pragma unroll
                for (int i = 0; i < 16; ++i) acc2[i] = fmul2(acc2[i], a2);
            }
            const float p = valid ? __expf(s - m) : 0.f;
            l += p;
            const float2 p2 = make_float2(p, p);
            #pragma unroll
            for (int i = 0; i < 8; ++i) {
                const float4 vv = vs[j][i * 2 + half];
                acc2[2 * i]     = ffma2(p2, make_float2(vv.x, vv.y), acc2[2 * i]);
                acc2[2 * i + 1] = ffma2(p2, make_float2(vv.z, vv.w), acc2[2 * i + 1]);
            }
        }
        __syncthreads();
    }

    const float inv = 1.0f / l;
    const float2 inv2 = make_float2(inv, inv);
    float4* op = reinterpret_cast<float4*>(
        O + ((size_t)(b * SEQ + qi) * 16 + h) * 64 + half * 32);
    #pragma unroll
    for (int i = 0; i < 8; ++i) {
        const float2 o0 = fmul2(acc2[2 * i], inv2);
        const float2 o1 = fmul2(acc2[2 * i + 1], inv2);
        op[i] = make_float4(o0.x, o0.y, o1.x, o1.y);
    }
}

// ---------------------------------------------------------------------------
// Inputs: x, start_pos, freqs_cos, freqs_sin, mask, wq, wk, wv, wo
// start_pos = 0 and mask is exactly causal tril(-1e9) -> handled analytically.
// ---------------------------------------------------------------------------
extern "C" void kernel_launch(void* const* d_in, const int* in_sizes, int n_in,
                              void* d_out, int out_size)
{
    const float* x  = (const float*)d_in[0];
    const float* fc = (const float*)d_in[2];
    const float* fs = (const float*)d_in[3];
    const float* wq = (const float*)d_in[5];
    const float* wk = (const float*)d_in[6];
    const float* wv = (const float*)d_in[7];
    const float* wo = (const float*)d_in[8];
    float* out = (float*)d_out;

    float *gq, *gk, *gv, *ga;
    cudaGetSymbolAddress((void**)&gq, g_q);
    cudaGetSymbolAddress((void**)&gk, g_k);
    cudaGetSymbolAddress((void**)&gv, g_v);
    cudaGetSymbolAddress((void**)&ga, g_attn);

    // Fused QKV projection (+RoPE, +1/sqrt(d) on Q)
    qkv_kernel<<<dim3(12, 32), 256>>>(x, wq, wk, wv, gq, gk, gv, fc, fs);
    // Flash attention: grid (qtiles=16, heads=16, batch=2), 256 thr = 128 queries
    attn_kernel<<<dim3(16, 16, 2), 256>>>(gq, gk, gv, ga);
    // Output projection -> d_out
    oproj_kernel<<<dim3(8, 32), 256>>>(ga, wo, out);
}

// round 4
// speedup vs baseline: 1.5434x; 1.2142x over previous
#include <cuda_runtime.h>
#include <cuda_bf16.h>
#include <cstddef>
#include <cstdint>

#define SEQ    2048
#define KDIM   1024

// ---------------------------------------------------------------------------
// Device scratch (no allocation allowed)
// ---------------------------------------------------------------------------
__device__ __nv_bfloat16 g_xh[4096 * 1024];
__device__ __nv_bfloat16 g_xl[4096 * 1024];
__device__ __nv_bfloat16 g_wqt_h[1024 * 1024], g_wqt_l[1024 * 1024];  // [N,K]
__device__ __nv_bfloat16 g_wkt_h[256 * 1024],  g_wkt_l[256 * 1024];
__device__ __nv_bfloat16 g_wvt_h[256 * 1024],  g_wvt_l[256 * 1024];
__device__ __nv_bfloat16 g_wot_h[1024 * 1024], g_wot_l[1024 * 1024];
__device__ float g_q[4096 * 1024];   // RoPE'd, pre-scaled by 0.125
__device__ float g_k[4096 * 256];
__device__ float g_v[4096 * 256];
__device__ __nv_bfloat16 g_oh[4096 * 1024];  // attention out hi/lo
__device__ __nv_bfloat16 g_ol[4096 * 1024];

// ---------------------------------------------------------------------------
// PTX helpers (all architecture-generic: work on plain sm_103 target)
// ---------------------------------------------------------------------------
__device__ __forceinline__ float2 ffma2(float2 a, float2 b, float2 c) {
    unsigned long long au = *reinterpret_cast<unsigned long long*>(&a);
    unsigned long long bu = *reinterpret_cast<unsigned long long*>(&b);
    unsigned long long cu = *reinterpret_cast<unsigned long long*>(&c);
    unsigned long long du;
    asm("fma.rn.f32x2 %0, %1, %2, %3;" : "=l"(du) : "l"(au), "l"(bu), "l"(cu));
    return *reinterpret_cast<float2*>(&du);
}
__device__ __forceinline__ float2 fmul2(float2 a, float2 b) {
    unsigned long long au = *reinterpret_cast<unsigned long long*>(&a);
    unsigned long long bu = *reinterpret_cast<unsigned long long*>(&b);
    unsigned long long du;
    asm("mul.rn.f32x2 %0, %1, %2;" : "=l"(du) : "l"(au), "l"(bu));
    return *reinterpret_cast<float2*>(&du);
}

__device__ __forceinline__ void ldsm_x4(uint32_t r[4], uint32_t addr) {
    asm volatile("ldmatrix.sync.aligned.m8n8.x4.shared.b16 {%0,%1,%2,%3}, [%4];"
        : "=r"(r[0]), "=r"(r[1]), "=r"(r[2]), "=r"(r[3]) : "r"(addr));
}
__device__ __forceinline__ void mma16816(float c[4], const uint32_t a[4], const uint32_t b[2]) {
    asm volatile(
        "mma.sync.aligned.m16n8k16.row.col.f32.bf16.bf16.f32 "
        "{%0,%1,%2,%3}, {%4,%5,%6,%7}, {%8,%9}, {%0,%1,%2,%3};"
        : "+f"(c[0]), "+f"(c[1]), "+f"(c[2]), "+f"(c[3])
        : "r"(a[0]), "r"(a[1]), "r"(a[2]), "r"(a[3]), "r"(b[0]), "r"(b[1]));
}
__device__ __forceinline__ void cp16(uint32_t dst, const void* src) {
    asm volatile("cp.async.cg.shared.global [%0], [%1], 16;" :: "r"(dst), "l"(src));
}

// ---------------------------------------------------------------------------
// Split-bf16 HMMA GEMM: C[M,N] = A[M,1024] @ B[N,1024]^T  (B row = N index)
// C = Ah*Bh + Ah*Bl + Al*Bh. CTA tile 128x128, 8 warps (warp tile 64x32),
// K-chunk 16, cp.async double buffer. rmode: 0 plain, 1 RoPE, 2 RoPE+0.125.
// ---------------------------------------------------------------------------
__device__ __forceinline__ void gemm_hmma(
    const __nv_bfloat16* __restrict__ Ah, const __nv_bfloat16* __restrict__ Al,
    const __nv_bfloat16* __restrict__ Bh, const __nv_bfloat16* __restrict__ Bl,
    float* __restrict__ C, int N, int brow, int bcol, int rmode,
    const float* __restrict__ fc, const float* __restrict__ fs)
{
    // [stage][which 0=Ah 1=Al 2=Bh 3=Bl][128 rows][16 bf16]  (32 KB)
    __shared__ char sm[2][4][4096];
    const uint32_t sb = (uint32_t)__cvta_generic_to_shared(&sm[0][0][0]);

    const int tid  = threadIdx.x;
    const int wid  = tid >> 5;
    const int lane = tid & 31;
    const int m_base = (wid >> 2) * 64;   // 2 warp-rows
    const int n_base = (wid & 3) * 32;    // 4 warp-cols

    // loader: one 16B chunk per tile per thread
    const int lrow   = tid >> 1;
    const int lhalf  = tid & 1;
    const int lchunk = lhalf ^ ((lrow >> 2) & 1);          // xor swizzle
    const uint32_t ldst = (uint32_t)(lrow << 5) + (uint32_t)(lchunk << 4);
    const __nv_bfloat16* srcs[4] = {
        Ah + (size_t)(brow + lrow) * KDIM + lhalf * 8,
        Al + (size_t)(brow + lrow) * KDIM + lhalf * 8,
        Bh + (size_t)(bcol + lrow) * KDIM + lhalf * 8,
        Bl + (size_t)(bcol + lrow) * KDIM + lhalf * 8 };

    float acc[4][4][4];
    #pragma unroll
    for (int mi = 0; mi < 4; ++mi)
        #pragma unroll
        for (int nj = 0; nj < 4; ++nj)
            #pragma unroll
            for (int e = 0; e < 4; ++e) acc[mi][nj][e] = 0.f;

    // ldmatrix addresses (stage-relative)
    const int arow0  = (lane & 15);
    const int akoff  = (lane >> 4);            // 0/1 -> k 0-7 / 8-15
    const int brw    = ((lane >> 4) << 3) + (lane & 7);    // n within 16
    const int bkoff  = ((lane >> 3) & 1);

    auto a_addr = [&](int st, int h, int mi) -> uint32_t {
        const int r = m_base + mi * 16 + arow0;
        const int c = akoff ^ ((r >> 2) & 1);
        return sb + (uint32_t)(st * 16384 + h * 4096 + (r << 5) + (c << 4));
    };
    auto b_addr = [&](int st, int h, int g) -> uint32_t {   // g: n-group of 16
        const int r = n_base + g * 16 + brw;
        const int c = bkoff ^ ((r >> 2) & 1);
        return sb + (uint32_t)(st * 16384 + (2 + h) * 4096 + (r << 5) + (c << 4));
    };

    const int NCH = KDIM / 16;   // 64

    // prologue: chunk 0 -> stage 0
    #pragma unroll
    for (int w = 0; w < 4; ++w)
        cp16(sb + (uint32_t)(w * 4096) + ldst, srcs[w]);
    asm volatile("cp.async.commit_group;");

    #pragma unroll 1
    for (int c = 0; c < NCH; ++c) {
        const int cur = c & 1;
        if (c + 1 < NCH) {
            const uint32_t stoff = (uint32_t)((cur ^ 1) * 16384);
            #pragma unroll
            for (int w = 0; w < 4; ++w)
                cp16(sb + stoff + (uint32_t)(w * 4096) + ldst, srcs[w] + (c + 1) * 16);
            asm volatile("cp.async.commit_group;");
            asm volatile("cp.async.wait_group 1;");
        } else {
            asm volatile("cp.async.wait_group 0;");
        }
        __syncthreads();

        // B fragments: [h][nj][2]
        uint32_t bf[2][4][2];
        #pragma unroll
        for (int h = 0; h < 2; ++h)
            #pragma unroll
            for (int g = 0; g < 2; ++g) {
                uint32_t r4[4];
                ldsm_x4(r4, b_addr(cur, h, g));
                bf[h][g * 2][0]     = r4[0]; bf[h][g * 2][1]     = r4[1];
                bf[h][g * 2 + 1][0] = r4[2]; bf[h][g * 2 + 1][1] = r4[3];
            }

        #pragma unroll
        for (int mi = 0; mi < 4; ++mi) {
            uint32_t ah[4], al[4];
            ldsm_x4(ah, a_addr(cur, 0, mi));
            ldsm_x4(al, a_addr(cur, 1, mi));
            #pragma unroll
            for (int nj = 0; nj < 4; ++nj) {
                mma16816(acc[mi][nj], ah, bf[0][nj]);   // Ah*Bh
                mma16816(acc[mi][nj], ah, bf[1][nj]);   // Ah*Bl
                mma16816(acc[mi][nj], al, bf[0][nj]);   // Al*Bh
            }
        }
        __syncthreads();
    }

    // epilogue: C frag: {c0,c1} at (row, col..col+1), {c2,c3} at (row+8, ...)
    const int rbase = brow + m_base + (lane >> 2);
    const int cbase = bcol + n_base + (lane & 3) * 2;
    #pragma unroll
    for (int mi = 0; mi < 4; ++mi) {
        #pragma unroll
        for (int half = 0; half < 2; ++half) {
            const int r = rbase + mi * 16 + half * 8;
            const int srow = r & (SEQ - 1);
            #pragma unroll
            for (int nj = 0; nj < 4; ++nj) {
                const int col = cbase + nj * 8;
                float v0 = acc[mi][nj][half * 2];
                float v1 = acc[mi][nj][half * 2 + 1];
                if (rmode > 0) {
                    const int pair = (col & 63) >> 1;
                    const float cc = fc[srow * 32 + pair];
                    const float ss = fs[srow * 32 + pair];
                    float orv = v0 * cc - v1 * ss;
                    float oiv = v0 * ss + v1 * cc;
                    if (rmode == 2) { orv *= 0.125f; oiv *= 0.125f; }
                    v0 = orv; v1 = oiv;
                }
                *reinterpret_cast<float2*>(C + (size_t)r * N + col) = make_float2(v0, v1);
            }
        }
    }
}

// Fused QKV projection: bx 0-7 Q(+RoPE+scale), 8-9 K(+RoPE), 10-11 V
__global__ void __launch_bounds__(256) qkv_hmma_kernel(
    const float* __restrict__ fc, const float* __restrict__ fs)
{
    const int bx   = blockIdx.x;
    const int brow = blockIdx.y * 128;
    if (bx < 8)
        gemm_hmma(g_xh, g_xl, g_wqt_h, g_wqt_l, g_q, 1024, brow, bx * 128, 2, fc, fs);
    else if (bx < 10)
        gemm_hmma(g_xh, g_xl, g_wkt_h, g_wkt_l, g_k, 256, brow, (bx - 8) * 128, 1, fc, fs);
    else
        gemm_hmma(g_xh, g_xl, g_wvt_h, g_wvt_l, g_v, 256, brow, (bx - 10) * 128, 0, nullptr, nullptr);
}

__global__ void __launch_bounds__(256) oproj_hmma_kernel(float* __restrict__ out)
{
    gemm_hmma(g_oh, g_ol, g_wot_h, g_wot_l, out, 1024,
              blockIdx.y * 128, blockIdx.x * 128, 0, nullptr, nullptr);
}

// ---------------------------------------------------------------------------
// Prep: x -> bf16 hi/lo
// ---------------------------------------------------------------------------
__global__ void __launch_bounds__(256) xconv_kernel(const float* __restrict__ x)
{
    const int i = blockIdx.x * 256 + threadIdx.x;   // over 1M float4s
    const float4 v = reinterpret_cast<const float4*>(x)[i];
    float f[4] = {v.x, v.y, v.z, v.w};
    __nv_bfloat16 h[4], l[4];
    #pragma unroll
    for (int j = 0; j < 4; ++j) {
        h[j] = __float2bfloat16(f[j]);
        l[j] = __float2bfloat16(f[j] - __bfloat162float(h[j]));
    }
    reinterpret_cast<__nv_bfloat162*>(g_xh)[i * 2]     = __nv_bfloat162(h[0], h[1]);
    reinterpret_cast<__nv_bfloat162*>(g_xh)[i * 2 + 1] = __nv_bfloat162(h[2], h[3]);
    reinterpret_cast<__nv_bfloat162*>(g_xl)[i * 2]     = __nv_bfloat162(l[0], l[1]);
    reinterpret_cast<__nv_bfloat162*>(g_xl)[i * 2 + 1] = __nv_bfloat162(l[2], l[3]);
}

// Prep: W[K=1024, N] fp32 -> W^T hi/lo bf16 [N, 1024]
__global__ void __launch_bounds__(256) wconv_kernel(
    const float* __restrict__ W, __nv_bfloat16* __restrict__ Th,
    __nv_bfloat16* __restrict__ Tl, int N)
{
    __shared__ float t[32][33];
    const int n0 = blockIdx.x * 32, k0 = blockIdx.y * 32;
    const int tx = threadIdx.x & 31, ty = threadIdx.x >> 5;   // 32 x 8
    #pragma unroll
    for (int i = 0; i < 32; i += 8)
        t[ty + i][tx] = W[(size_t)(k0 + ty + i) * N + n0 + tx];
    __syncthreads();
    #pragma unroll
    for (int i = 0; i < 32; i += 8) {
        const float v = t[tx][ty + i];
        const __nv_bfloat16 h = __float2bfloat16(v);
        const size_t o = (size_t)(n0 + ty + i) * 1024 + k0 + tx;
        Th[o] = h;
        Tl[o] = __float2bfloat16(v - __bfloat162float(h));
    }
}

// ---------------------------------------------------------------------------
// Flash attention (causal, GQA 16q/4kv, hd 64, fp32 f32x2). 2 thr/query.
// Writes output as bf16 hi/lo for the HMMA output projection.
// ---------------------------------------------------------------------------
__global__ void __launch_bounds__(256, 2) attn_kernel(
    const float* __restrict__ Q, const float* __restrict__ Kg,
    const float* __restrict__ Vg)
{
    const int b    = blockIdx.z;
    const int h    = blockIdx.y;
    const int qt   = (int)gridDim.x - 1 - blockIdx.x;   // heavy tiles first
    const int t    = threadIdx.x;
    const int ql   = t >> 1;
    const int half = t & 1;
    const int qi   = qt * 128 + ql;
    const int hk   = h >> 2;

    __shared__ float4 ks[64][16];   // interleaved: [j][(d&7)*2 + (d>>3)]
    __shared__ float4 vs[64][16];

    float2 q2[16];
    {
        const float4* qp4 = reinterpret_cast<const float4*>(
            Q + ((size_t)(b * SEQ + qi) * 16 + h) * 64 + half * 32);
        #pragma unroll
        for (int i = 0; i < 8; ++i) {
            float4 v = qp4[i];
            q2[2 * i]     = make_float2(v.x, v.y);
            q2[2 * i + 1] = make_float2(v.z, v.w);
        }
    }

    float2 acc2[16];
    #pragma unroll
    for (int i = 0; i < 16; ++i) acc2[i] = make_float2(0.f, 0.f);
    float m = -1e30f, l = 0.f;

    const int wtop = ((t >> 5) << 4) + 15;
    const int qtop = qt * 128 + wtop;

    const int ntiles = qt * 2 + 2;
    for (int kt = 0; kt < ntiles; ++kt) {
        const float4* kbase = reinterpret_cast<const float4*>(
            Kg + ((size_t)(b * SEQ + kt * 64) * 4 + hk) * 64);
        const float4* vbase = reinterpret_cast<const float4*>(
            Vg + ((size_t)(b * SEQ + kt * 64) * 4 + hk) * 64);
        #pragma unroll
        for (int it = 0; it < 4; ++it) {
            const int idx = t + it * 256;
            const int j   = idx >> 4;
            const int d   = idx & 15;
            const int ds  = ((d & 7) << 1) | (d >> 3);
            ks[j][ds] = kbase[(size_t)j * 64 + d];
            vs[j][ds] = vbase[(size_t)j * 64 + d];
        }
        __syncthreads();

        int jw = qtop - kt * 64 + 1;
        if (jw > 64) jw = 64;
        const int jmine = qi - kt * 64;

        for (int j = 0; j < jw; ++j) {
            float2 s2 = make_float2(0.f, 0.f);
            #pragma unroll
            for (int i = 0; i < 8; ++i) {
                const float4 kv = ks[j][i * 2 + half];
                s2 = ffma2(q2[2 * i],     make_float2(kv.x, kv.y), s2);
                s2 = ffma2(q2[2 * i + 1], make_float2(kv.z, kv.w), s2);
            }
            float s = s2.x + s2.y;
            s += __shfl_xor_sync(0xffffffffu, s, 1);

            const bool valid = (j <= jmine);
            if (valid && s > m) {
                const float alpha = __expf(m - s);
                m = s;
                l *= alpha;
                const float2 a2 = make_float2(alpha, alpha);
                #pragma unroll
                for (int i = 0; i < 16; ++i) acc2[i] = fmul2(acc2[i], a2);
            }
            const float p = valid ? __expf(s - m) : 0.f;
            l += p;
            const float2 p2 = make_float2(p, p);
            #pragma unroll
            for (int i = 0; i < 8; ++i) {
                const float4 vv = vs[j][i * 2 + half];
                acc2[2 * i]     = ffma2(p2, make_float2(vv.x, vv.y), acc2[2 * i]);
                acc2[2 * i + 1] = ffma2(p2, make_float2(vv.z, vv.w), acc2[2 * i + 1]);
            }
        }
        __syncthreads();
    }

    const float inv = 1.0f / l;
    const size_t obase = ((size_t)(b * SEQ + qi) * 16 + h) * 64 + half * 32;
    __nv_bfloat162* oh2 = reinterpret_cast<__nv_bfloat162*>(g_oh + obase);
    __nv_bfloat162* ol2 = reinterpret_cast<__nv_bfloat162*>(g_ol + obase);
    #pragma unroll
    for (int i = 0; i < 16; ++i) {
        const float a = acc2[i].x * inv;
        const float c = acc2[i].y * inv;
        const __nv_bfloat16 ha = __float2bfloat16(a);
        const __nv_bfloat16 hc = __float2bfloat16(c);
        oh2[i] = __nv_bfloat162(ha, hc);
        ol2[i] = __nv_bfloat162(__float2bfloat16(a - __bfloat162float(ha)),
                                __float2bfloat16(c - __bfloat162float(hc)));
    }
}

// ---------------------------------------------------------------------------
// Inputs: x, start_pos, freqs_cos, freqs_sin, mask, wq, wk, wv, wo
// ---------------------------------------------------------------------------
extern "C" void kernel_launch(void* const* d_in, const int* in_sizes, int n_in,
                              void* d_out, int out_size)
{
    const float* x  = (const float*)d_in[0];
    const float* fc = (const float*)d_in[2];
    const float* fs = (const float*)d_in[3];
    const float* wq = (const float*)d_in[5];
    const float* wk = (const float*)d_in[6];
    const float* wv = (const float*)d_in[7];
    const float* wo = (const float*)d_in[8];
    float* out = (float*)d_out;

    float *gq, *gk, *gv;
    cudaGetSymbolAddress((void**)&gq, g_q);
    cudaGetSymbolAddress((void**)&gk, g_k);
    cudaGetSymbolAddress((void**)&gv, g_v);
    __nv_bfloat16 *wqth, *wqtl, *wkth, *wktl, *wvth, *wvtl, *woth, *wotl;
    cudaGetSymbolAddress((void**)&wqth, g_wqt_h);
    cudaGetSymbolAddress((void**)&wqtl, g_wqt_l);
    cudaGetSymbolAddress((void**)&wkth, g_wkt_h);
    cudaGetSymbolAddress((void**)&wktl, g_wkt_l);
    cudaGetSymbolAddress((void**)&wvth, g_wvt_h);
    cudaGetSymbolAddress((void**)&wvtl, g_wvt_l);
    cudaGetSymbolAddress((void**)&woth, g_wot_h);
    cudaGetSymbolAddress((void**)&wotl, g_wot_l);

    // Prep: split x, transpose+split weights
    xconv_kernel<<<4096, 256>>>(x);
    wconv_kernel<<<dim3(32, 32), 256>>>(wq, wqth, wqtl, 1024);
    wconv_kernel<<<dim3(8, 32),  256>>>(wk, wkth, wktl, 256);
    wconv_kernel<<<dim3(8, 32),  256>>>(wv, wvth, wvtl, 256);
    wconv_kernel<<<dim3(32, 32), 256>>>(wo, woth, wotl, 1024);

    // QKV projection (HMMA split-bf16, RoPE fused)
    qkv_hmma_kernel<<<dim3(12, 32), 256>>>(fc, fs);
    // Flash attention
    attn_kernel<<<dim3(16, 16, 2), 256>>>(gq, gk, gv);
    // Output projection (HMMA) -> d_out
    oproj_hmma_kernel<<<dim3(8, 32), 256>>>(out);
}

// round 5
// speedup vs baseline: 3.6261x; 2.3495x over previous
#include <cuda_runtime.h>
#include <cuda_bf16.h>
#include <cstddef>
#include <cstdint>

#define SEQ    2048
#define KDIM   1024

// ---------------------------------------------------------------------------
// Device scratch (no allocation allowed)
// ---------------------------------------------------------------------------
__device__ __nv_bfloat16 g_xh[4096 * 1024];
__device__ __nv_bfloat16 g_xl[4096 * 1024];
__device__ __nv_bfloat16 g_wqt_h[1024 * 1024], g_wqt_l[1024 * 1024];  // [N,K]
__device__ __nv_bfloat16 g_wkt_h[256 * 1024],  g_wkt_l[256 * 1024];
__device__ __nv_bfloat16 g_wvt_h[256 * 1024],  g_wvt_l[256 * 1024];
__device__ __nv_bfloat16 g_wot_h[1024 * 1024], g_wot_l[1024 * 1024];
__device__ __nv_bfloat16 g_qh[4096 * 1024], g_ql[4096 * 1024];  // RoPE'd, ×0.125
__device__ __nv_bfloat16 g_kh[4096 * 256],  g_kl[4096 * 256];   // RoPE'd
__device__ float g_v[4096 * 256];
__device__ __nv_bfloat16 g_vth[8 * 64 * 2048], g_vtl[8 * 64 * 2048]; // V^T [bhk][d][s]
__device__ __nv_bfloat16 g_oh[4096 * 1024], g_ol[4096 * 1024];  // attn out hi/lo

// ---------------------------------------------------------------------------
// PTX helpers (architecture-generic; plain sm_103 target)
// ---------------------------------------------------------------------------
__device__ __forceinline__ void ldsm_x4(uint32_t r[4], uint32_t addr) {
    asm volatile("ldmatrix.sync.aligned.m8n8.x4.shared.b16 {%0,%1,%2,%3}, [%4];"
        : "=r"(r[0]), "=r"(r[1]), "=r"(r[2]), "=r"(r[3]) : "r"(addr));
}
__device__ __forceinline__ void mma16816(float c[4], const uint32_t a[4], const uint32_t b[2]) {
    asm volatile(
        "mma.sync.aligned.m16n8k16.row.col.f32.bf16.bf16.f32 "
        "{%0,%1,%2,%3}, {%4,%5,%6,%7}, {%8,%9}, {%0,%1,%2,%3};"
        : "+f"(c[0]), "+f"(c[1]), "+f"(c[2]), "+f"(c[3])
        : "r"(a[0]), "r"(a[1]), "r"(a[2]), "r"(a[3]), "r"(b[0]), "r"(b[1]));
}
__device__ __forceinline__ void cp16(uint32_t dst, const void* src) {
    asm volatile("cp.async.cg.shared.global [%0], [%1], 16;" :: "r"(dst), "l"(src));
}
__device__ __forceinline__ uint32_t pack_bf16(float lo, float hi) {
    uint32_t r;
    asm("cvt.rn.bf16x2.f32 %0, %1, %2;" : "=r"(r) : "f"(hi), "f"(lo));
    return r;
}

// ---------------------------------------------------------------------------
// Split-bf16 HMMA GEMM: C[M,N] = A[M,1024] @ B[N,1024]^T.
// OMODE: 0 = fp32 out; 1 = RoPE -> bf16 hi/lo out; 2 = RoPE+0.125 -> bf16 hi/lo
// CTA 128x128, 8 warps (warp 64x32), K-chunk 16, cp.async double buffer.
// ---------------------------------------------------------------------------
template <int OMODE>
__device__ __forceinline__ void gemm_hmma(
    const __nv_bfloat16* __restrict__ Ah, const __nv_bfloat16* __restrict__ Al,
    const __nv_bfloat16* __restrict__ Bh, const __nv_bfloat16* __restrict__ Bl,
    float* __restrict__ Cf, __nv_bfloat16* __restrict__ Ch, __nv_bfloat16* __restrict__ Cl,
    int N, int brow, int bcol,
    const float* __restrict__ fc, const float* __restrict__ fs)
{
    __shared__ char sm[2][4][4096];
    const uint32_t sb = (uint32_t)__cvta_generic_to_shared(&sm[0][0][0]);

    const int tid  = threadIdx.x;
    const int wid  = tid >> 5;
    const int lane = tid & 31;
    const int m_base = (wid >> 2) * 64;
    const int n_base = (wid & 3) * 32;

    const int lrow   = tid >> 1;
    const int lhalf  = tid & 1;
    const int lchunk = lhalf ^ ((lrow >> 2) & 1);
    const uint32_t ldst = (uint32_t)(lrow << 5) + (uint32_t)(lchunk << 4);
    const __nv_bfloat16* srcs[4] = {
        Ah + (size_t)(brow + lrow) * KDIM + lhalf * 8,
        Al + (size_t)(brow + lrow) * KDIM + lhalf * 8,
        Bh + (size_t)(bcol + lrow) * KDIM + lhalf * 8,
        Bl + (size_t)(bcol + lrow) * KDIM + lhalf * 8 };

    float acc[4][4][4];
    #pragma unroll
    for (int mi = 0; mi < 4; ++mi)
        #pragma unroll
        for (int nj = 0; nj < 4; ++nj)
            #pragma unroll
            for (int e = 0; e < 4; ++e) acc[mi][nj][e] = 0.f;

    const int arow0 = (lane & 15);
    const int akoff = (lane >> 4);
    const int brw   = ((lane >> 4) << 3) + (lane & 7);
    const int bkoff = ((lane >> 3) & 1);

    auto a_addr = [&](int st, int h, int mi) -> uint32_t {
        const int r = m_base + mi * 16 + arow0;
        const int c = akoff ^ ((r >> 2) & 1);
        return sb + (uint32_t)(st * 16384 + h * 4096 + (r << 5) + (c << 4));
    };
    auto b_addr = [&](int st, int h, int g) -> uint32_t {
        const int r = n_base + g * 16 + brw;
        const int c = bkoff ^ ((r >> 2) & 1);
        return sb + (uint32_t)(st * 16384 + (2 + h) * 4096 + (r << 5) + (c << 4));
    };

    const int NCH = KDIM / 16;

    #pragma unroll
    for (int w = 0; w < 4; ++w)
        cp16(sb + (uint32_t)(w * 4096) + ldst, srcs[w]);
    asm volatile("cp.async.commit_group;");

    #pragma unroll 1
    for (int c = 0; c < NCH; ++c) {
        const int cur = c & 1;
        if (c + 1 < NCH) {
            const uint32_t stoff = (uint32_t)((cur ^ 1) * 16384);
            #pragma unroll
            for (int w = 0; w < 4; ++w)
                cp16(sb + stoff + (uint32_t)(w * 4096) + ldst, srcs[w] + (c + 1) * 16);
            asm volatile("cp.async.commit_group;");
            asm volatile("cp.async.wait_group 1;");
        } else {
            asm volatile("cp.async.wait_group 0;");
        }
        __syncthreads();

        uint32_t bf[2][4][2];
        #pragma unroll
        for (int h = 0; h < 2; ++h)
            #pragma unroll
            for (int g = 0; g < 2; ++g) {
                uint32_t r4[4];
                ldsm_x4(r4, b_addr(cur, h, g));
                bf[h][g * 2][0]     = r4[0]; bf[h][g * 2][1]     = r4[1];
                bf[h][g * 2 + 1][0] = r4[2]; bf[h][g * 2 + 1][1] = r4[3];
            }

        #pragma unroll
        for (int mi = 0; mi < 4; ++mi) {
            uint32_t ah[4], al[4];
            ldsm_x4(ah, a_addr(cur, 0, mi));
            ldsm_x4(al, a_addr(cur, 1, mi));
            #pragma unroll
            for (int nj = 0; nj < 4; ++nj) {
                mma16816(acc[mi][nj], ah, bf[0][nj]);
                mma16816(acc[mi][nj], ah, bf[1][nj]);
                mma16816(acc[mi][nj], al, bf[0][nj]);
            }
        }
        __syncthreads();
    }

    const int rbase = brow + m_base + (lane >> 2);
    const int cbase = bcol + n_base + (lane & 3) * 2;
    #pragma unroll
    for (int mi = 0; mi < 4; ++mi) {
        #pragma unroll
        for (int half = 0; half < 2; ++half) {
            const int r = rbase + mi * 16 + half * 8;
            const int srow = r & (SEQ - 1);
            #pragma unroll
            for (int nj = 0; nj < 4; ++nj) {
                const int col = cbase + nj * 8;
                float v0 = acc[mi][nj][half * 2];
                float v1 = acc[mi][nj][half * 2 + 1];
                if (OMODE > 0) {
                    const int pair = (col & 63) >> 1;
                    const float cc = fc[srow * 32 + pair];
                    const float ss = fs[srow * 32 + pair];
                    float orv = v0 * cc - v1 * ss;
                    float oiv = v0 * ss + v1 * cc;
                    if (OMODE == 2) { orv *= 0.125f; oiv *= 0.125f; }
                    v0 = orv; v1 = oiv;
                    const __nv_bfloat16 h0 = __float2bfloat16(v0);
                    const __nv_bfloat16 h1 = __float2bfloat16(v1);
                    *reinterpret_cast<__nv_bfloat162*>(Ch + (size_t)r * N + col) =
                        __nv_bfloat162(h0, h1);
                    *reinterpret_cast<__nv_bfloat162*>(Cl + (size_t)r * N + col) =
                        __nv_bfloat162(__float2bfloat16(v0 - __bfloat162float(h0)),
                                       __float2bfloat16(v1 - __bfloat162float(h1)));
                } else {
                    *reinterpret_cast<float2*>(Cf + (size_t)r * N + col) = make_float2(v0, v1);
                }
            }
        }
    }
}

__global__ void __launch_bounds__(256) qkv_hmma_kernel(
    const float* __restrict__ fc, const float* __restrict__ fs)
{
    const int bx   = blockIdx.x;
    const int brow = blockIdx.y * 128;
    if (bx < 8)
        gemm_hmma<2>(g_xh, g_xl, g_wqt_h, g_wqt_l, nullptr, g_qh, g_ql,
                     1024, brow, bx * 128, fc, fs);
    else if (bx < 10)
        gemm_hmma<1>(g_xh, g_xl, g_wkt_h, g_wkt_l, nullptr, g_kh, g_kl,
                     256, brow, (bx - 8) * 128, fc, fs);
    else
        gemm_hmma<0>(g_xh, g_xl, g_wvt_h, g_wvt_l, g_v, nullptr, nullptr,
                     256, brow, (bx - 10) * 128, nullptr, nullptr);
}

__global__ void __launch_bounds__(256) oproj_hmma_kernel(float* __restrict__ out)
{
    gemm_hmma<0>(g_oh, g_ol, g_wot_h, g_wot_l, out, nullptr, nullptr,
                 1024, blockIdx.y * 128, blockIdx.x * 128, nullptr, nullptr);
}

// ---------------------------------------------------------------------------
// Prep kernels
// ---------------------------------------------------------------------------
__global__ void __launch_bounds__(256) xconv_kernel(const float* __restrict__ x)
{
    const int i = blockIdx.x * 256 + threadIdx.x;
    const float4 v = reinterpret_cast<const float4*>(x)[i];
    float f[4] = {v.x, v.y, v.z, v.w};
    __nv_bfloat16 h[4], l[4];
    #pragma unroll
    for (int j = 0; j < 4; ++j) {
        h[j] = __float2bfloat16(f[j]);
        l[j] = __float2bfloat16(f[j] - __bfloat162float(h[j]));
    }
    reinterpret_cast<__nv_bfloat162*>(g_xh)[i * 2]     = __nv_bfloat162(h[0], h[1]);
    reinterpret_cast<__nv_bfloat162*>(g_xh)[i * 2 + 1] = __nv_bfloat162(h[2], h[3]);
    reinterpret_cast<__nv_bfloat162*>(g_xl)[i * 2]     = __nv_bfloat162(l[0], l[1]);
    reinterpret_cast<__nv_bfloat162*>(g_xl)[i * 2 + 1] = __nv_bfloat162(l[2], l[3]);
}

__global__ void __launch_bounds__(256) wconv_kernel(
    const float* __restrict__ W, __nv_bfloat16* __restrict__ Th,
    __nv_bfloat16* __restrict__ Tl, int N)
{
    __shared__ float t[32][33];
    const int n0 = blockIdx.x * 32, k0 = blockIdx.y * 32;
    const int tx = threadIdx.x & 31, ty = threadIdx.x >> 5;
    #pragma unroll
    for (int i = 0; i < 32; i += 8)
        t[ty + i][tx] = W[(size_t)(k0 + ty + i) * N + n0 + tx];
    __syncthreads();
    #pragma unroll
    for (int i = 0; i < 32; i += 8) {
        const float v = t[tx][ty + i];
        const __nv_bfloat16 h = __float2bfloat16(v);
        const size_t o = (size_t)(n0 + ty + i) * 1024 + k0 + tx;
        Th[o] = h;
        Tl[o] = __float2bfloat16(v - __bfloat162float(h));
    }
}

// V [b,s,hk,d] fp32 -> V^T hi/lo bf16 [(b*4+hk)][d][s]
__global__ void __launch_bounds__(256) vtrans_kernel()
{
    __shared__ float t[32][33];
    const int bhk = blockIdx.z;
    const int b = bhk >> 2, hk = bhk & 3;
    const int s0 = blockIdx.x * 32, d0 = blockIdx.y * 32;
    const int tx = threadIdx.x & 31, ty = threadIdx.x >> 5;
    #pragma unroll
    for (int i = 0; i < 32; i += 8)
        t[ty + i][tx] = g_v[(size_t)(b * SEQ + s0 + ty + i) * 256 + hk * 64 + d0 + tx];
    __syncthreads();
    #pragma unroll
    for (int i = 0; i < 32; i += 8) {
        const float v = t[tx][ty + i];
        const __nv_bfloat16 h = __float2bfloat16(v);
        const size_t o = (size_t)(bhk * 64 + d0 + ty + i) * SEQ + s0 + tx;
        g_vth[o] = h;
        g_vtl[o] = __float2bfloat16(v - __bfloat162float(h));
    }
}

// ---------------------------------------------------------------------------
// Tensor-core flash attention. CTA = 128 queries x one (b,h). 4 warps, each
// 32 query rows. K-tiles of 64 keys, double-buffered cp.async.
// smem: Qh 16K | Ql 16K | stage{0,1}: Kh 8K, Kl 8K, Vh 8K, Vl 8K  (96 KB)
// ---------------------------------------------------------------------------
#define ASM_Q   0
#define ASM_QL  16384
#define ASM_ST  32768
#define ASM_TOT 98304

__global__ void __launch_bounds__(128, 2) attn_mma_kernel()
{
    extern __shared__ char asmem[];
    const uint32_t sb = (uint32_t)__cvta_generic_to_shared(asmem);
    const int tid = threadIdx.x, w = tid >> 5, lane = tid & 31;
    const int b = blockIdx.z, h = blockIdx.y;
    const int qt = (int)gridDim.x - 1 - blockIdx.x;
    const int hk = h >> 2;
    const int q0 = qt * 128;
    const int ntiles = 2 * qt + 2;

    // --- Q tile load (once): 128 rows x 64 d, hi+lo ---
    {
        const size_t qoff = (size_t)(b * SEQ + q0 + tid) * 1024 + h * 64;
        #pragma unroll
        for (int c = 0; c < 8; ++c) {
            const uint32_t sw = (uint32_t)((c ^ (tid & 7)) << 4) + (uint32_t)(tid << 7);
            cp16(sb + ASM_Q  + sw, g_qh + qoff + c * 8);
            cp16(sb + ASM_QL + sw, g_ql + qoff + c * 8);
        }
        asm volatile("cp.async.commit_group;");
    }
    // --- stage loader ---
    auto load_stage = [&](int st, int kt) {
        const int row = tid >> 1;
        const int cb  = (tid & 1) * 4;
        const uint32_t so = sb + ASM_ST + (uint32_t)st * 32768;
        const size_t koff = (size_t)(b * SEQ + kt * 64 + row) * 256 + hk * 64;
        const size_t voff = (size_t)((b * 4 + hk) * 64 + row) * SEQ + kt * 64;
        #pragma unroll
        for (int i = 0; i < 4; ++i) {
            const int c = cb + i;
            const uint32_t sw = (uint32_t)((c ^ (row & 7)) << 4) + (uint32_t)(row << 7);
            cp16(so +         sw, g_kh + koff + c * 8);
            cp16(so + 8192  + sw, g_kl + koff + c * 8);
            cp16(so + 16384 + sw, g_vth + voff + c * 8);
            cp16(so + 24576 + sw, g_vtl + voff + c * 8);
        }
        asm volatile("cp.async.commit_group;");
    };
    load_stage(0, 0);

    float o[2][8][4];
    #pragma unroll
    for (int mi = 0; mi < 2; ++mi)
        #pragma unroll
        for (int nj = 0; nj < 8; ++nj)
            #pragma unroll
            for (int e = 0; e < 4; ++e) o[mi][nj][e] = 0.f;
    float mrow[4] = {-1e30f, -1e30f, -1e30f, -1e30f};
    float lrow[4] = {0.f, 0.f, 0.f, 0.f};

    const int arow = lane & 15, akoff = lane >> 4;
    const int brw  = ((lane >> 4) << 3) + (lane & 7);
    const int bkoff = (lane >> 3) & 1;

    #pragma unroll 1
    for (int kt = 0; kt < ntiles; ++kt) {
        const int st = kt & 1;
        if (kt + 1 < ntiles) {
            load_stage(st ^ 1, kt + 1);
            asm volatile("cp.async.wait_group 1;");
        } else {
            asm volatile("cp.async.wait_group 0;");
        }
        __syncthreads();
        const uint32_t so = sb + ASM_ST + (uint32_t)st * 32768;

        // ---- S = Q @ K^T (split bf16, 3 passes) ----
        float sc[2][8][4];
        #pragma unroll
        for (int mi = 0; mi < 2; ++mi)
            #pragma unroll
            for (int nj = 0; nj < 8; ++nj)
                #pragma unroll
                for (int e = 0; e < 4; ++e) sc[mi][nj][e] = 0.f;

        #pragma unroll
        for (int kc = 0; kc < 4; ++kc) {
            uint32_t qh[2][4], ql[2][4];
            #pragma unroll
            for (int mi = 0; mi < 2; ++mi) {
                const int r = w * 32 + mi * 16 + arow;
                const uint32_t ch = (uint32_t)(((2 * kc + akoff) ^ (r & 7)) << 4) +
                                    (uint32_t)(r << 7);
                ldsm_x4(qh[mi], sb + ASM_Q  + ch);
                ldsm_x4(ql[mi], sb + ASM_QL + ch);
            }
            uint32_t kbh[8][2], kbl[8][2];
            #pragma unroll
            for (int g = 0; g < 4; ++g) {
                const int r = g * 16 + brw;
                const uint32_t ch = (uint32_t)(((2 * kc + bkoff) ^ (r & 7)) << 4) +
                                    (uint32_t)(r << 7);
                uint32_t t4[4];
                ldsm_x4(t4, so + ch);
                kbh[g * 2][0] = t4[0]; kbh[g * 2][1] = t4[1];
                kbh[g * 2 + 1][0] = t4[2]; kbh[g * 2 + 1][1] = t4[3];
                ldsm_x4(t4, so + 8192 + ch);
                kbl[g * 2][0] = t4[0]; kbl[g * 2][1] = t4[1];
                kbl[g * 2 + 1][0] = t4[2]; kbl[g * 2 + 1][1] = t4[3];
            }
            #pragma unroll
            for (int mi = 0; mi < 2; ++mi)
                #pragma unroll
                for (int nj = 0; nj < 8; ++nj) {
                    mma16816(sc[mi][nj], qh[mi], kbh[nj]);
                    mma16816(sc[mi][nj], qh[mi], kbl[nj]);
                    mma16816(sc[mi][nj], ql[mi], kbh[nj]);
                }
        }

        // ---- causal mask (only partial tiles) ----
        const int qwbase = q0 + w * 32;
        if (kt * 64 + 63 > qwbase) {
            const int jb = kt * 64 + (lane & 3) * 2;
            const int qb = qwbase + (lane >> 2);
            #pragma unroll
            for (int mi = 0; mi < 2; ++mi)
                #pragma unroll
                for (int nj = 0; nj < 8; ++nj)
                    #pragma unroll
                    for (int e = 0; e < 4; ++e) {
                        const int j = jb + nj * 8 + (e & 1);
                        const int q = qb + mi * 16 + ((e >> 1) << 3);
                        if (j > q) sc[mi][nj][e] = -1e30f;
                    }
        }

        // ---- online softmax ----
        float tm[4] = {-1e30f, -1e30f, -1e30f, -1e30f};
        #pragma unroll
        for (int mi = 0; mi < 2; ++mi)
            #pragma unroll
            for (int nj = 0; nj < 8; ++nj)
                #pragma unroll
                for (int e = 0; e < 4; ++e) {
                    const int ri = mi * 2 + (e >> 1);
                    tm[ri] = fmaxf(tm[ri], sc[mi][nj][e]);
                }
        float alpha[4];
        #pragma unroll
        for (int ri = 0; ri < 4; ++ri) {
            tm[ri] = fmaxf(tm[ri], __shfl_xor_sync(0xffffffffu, tm[ri], 1));
            tm[ri] = fmaxf(tm[ri], __shfl_xor_sync(0xffffffffu, tm[ri], 2));
            const float nm = fmaxf(mrow[ri], tm[ri]);
            alpha[ri] = __expf(mrow[ri] - nm);
            mrow[ri] = nm;
            lrow[ri] *= alpha[ri];
        }
        #pragma unroll
        for (int mi = 0; mi < 2; ++mi)
            #pragma unroll
            for (int nj = 0; nj < 8; ++nj) {
                o[mi][nj][0] *= alpha[mi * 2];     o[mi][nj][1] *= alpha[mi * 2];
                o[mi][nj][2] *= alpha[mi * 2 + 1]; o[mi][nj][3] *= alpha[mi * 2 + 1];
            }
        #pragma unroll
        for (int mi = 0; mi < 2; ++mi)
            #pragma unroll
            for (int nj = 0; nj < 8; ++nj)
                #pragma unroll
                for (int e = 0; e < 4; ++e) {
                    const int ri = mi * 2 + (e >> 1);
                    const float p = __expf(sc[mi][nj][e] - mrow[ri]);
                    sc[mi][nj][e] = p;
                    lrow[ri] += p;
                }

        // ---- O += P @ V (split P, split V) ----
        #pragma unroll
        for (int kc = 0; kc < 4; ++kc) {
            uint32_t ah[2][4], al[2][4];
            #pragma unroll
            for (int mi = 0; mi < 2; ++mi) {
                const float* s0 = sc[mi][2 * kc];
                const float* s1 = sc[mi][2 * kc + 1];
                float r0, r1;
                ah[mi][0] = pack_bf16(s0[0], s0[1]);
                ah[mi][1] = pack_bf16(s0[2], s0[3]);
                ah[mi][2] = pack_bf16(s1[0], s1[1]);
                ah[mi][3] = pack_bf16(s1[2], s1[3]);
                // residuals
                const __nv_bfloat162* hp;
                hp = reinterpret_cast<const __nv_bfloat162*>(&ah[mi][0]);
                r0 = s0[0] - __bfloat162float(hp->x); r1 = s0[1] - __bfloat162float(hp->y);
                al[mi][0] = pack_bf16(r0, r1);
                hp = reinterpret_cast<const __nv_bfloat162*>(&ah[mi][1]);
                r0 = s0[2] - __bfloat162float(hp->x); r1 = s0[3] - __bfloat162float(hp->y);
                al[mi][1] = pack_bf16(r0, r1);
                hp = reinterpret_cast<const __nv_bfloat162*>(&ah[mi][2]);
                r0 = s1[0] - __bfloat162float(hp->x); r1 = s1[1] - __bfloat162float(hp->y);
                al[mi][2] = pack_bf16(r0, r1);
                hp = reinterpret_cast<const __nv_bfloat162*>(&ah[mi][3]);
                r0 = s1[2] - __bfloat162float(hp->x); r1 = s1[3] - __bfloat162float(hp->y);
                al[mi][3] = pack_bf16(r0, r1);
            }
            uint32_t vbh[8][2], vbl[8][2];
            #pragma unroll
            for (int g = 0; g < 4; ++g) {
                const int r = g * 16 + brw;
                const uint32_t ch = (uint32_t)(((2 * kc + bkoff) ^ (r & 7)) << 4) +
                                    (uint32_t)(r << 7);
                uint32_t t4[4];
                ldsm_x4(t4, so + 16384 + ch);
                vbh[g * 2][0] = t4[0]; vbh[g * 2][1] = t4[1];
                vbh[g * 2 + 1][0] = t4[2]; vbh[g * 2 + 1][1] = t4[3];
                ldsm_x4(t4, so + 24576 + ch);
                vbl[g * 2][0] = t4[0]; vbl[g * 2][1] = t4[1];
                vbl[g * 2 + 1][0] = t4[2]; vbl[g * 2 + 1][1] = t4[3];
            }
            #pragma unroll
            for (int mi = 0; mi < 2; ++mi)
                #pragma unroll
                for (int nj = 0; nj < 8; ++nj) {
                    mma16816(o[mi][nj], ah[mi], vbh[nj]);
                    mma16816(o[mi][nj], ah[mi], vbl[nj]);
                    mma16816(o[mi][nj], al[mi], vbh[nj]);
                }
        }
        __syncthreads();
    }

    // ---- epilogue: normalize + write bf16 hi/lo ----
    float linv[4];
    #pragma unroll
    for (int ri = 0; ri < 4; ++ri) {
        float l = lrow[ri];
        l += __shfl_xor_sync(0xffffffffu, l, 1);
        l += __shfl_xor_sync(0xffffffffu, l, 2);
        linv[ri] = 1.0f / l;
    }
    #pragma unroll
    for (int mi = 0; mi < 2; ++mi) {
        #pragma unroll
        for (int half = 0; half < 2; ++half) {
            const int rloc = w * 32 + mi * 16 + (lane >> 2) + half * 8;
            const size_t rg = (size_t)(b * SEQ + q0 + rloc) * 1024 + h * 64;
            const float inv = linv[mi * 2 + half];
            #pragma unroll
            for (int nj = 0; nj < 8; ++nj) {
                const int col = nj * 8 + (lane & 3) * 2;
                const float v0 = o[mi][nj][half * 2] * inv;
                const float v1 = o[mi][nj][half * 2 + 1] * inv;
                const __nv_bfloat16 h0 = __float2bfloat16(v0);
                const __nv_bfloat16 h1 = __float2bfloat16(v1);
                *reinterpret_cast<__nv_bfloat162*>(g_oh + rg + col) = __nv_bfloat162(h0, h1);
                *reinterpret_cast<__nv_bfloat162*>(g_ol + rg + col) =
                    __nv_bfloat162(__float2bfloat16(v0 - __bfloat162float(h0)),
                                   __float2bfloat16(v1 - __bfloat162float(h1)));
            }
        }
    }
}

// ---------------------------------------------------------------------------
// Inputs: x, start_pos, freqs_cos, freqs_sin, mask, wq, wk, wv, wo
// ---------------------------------------------------------------------------
extern "C" void kernel_launch(void* const* d_in, const int* in_sizes, int n_in,
                              void* d_out, int out_size)
{
    const float* x  = (const float*)d_in[0];
    const float* fc = (const float*)d_in[2];
    const float* fs = (const float*)d_in[3];
    const float* wq = (const float*)d_in[5];
    const float* wk = (const float*)d_in[6];
    const float* wv = (const float*)d_in[7];
    const float* wo = (const float*)d_in[8];
    float* out = (float*)d_out;

    __nv_bfloat16 *wqth, *wqtl, *wkth, *wktl, *wvth, *wvtl, *woth, *wotl;
    cudaGetSymbolAddress((void**)&wqth, g_wqt_h);
    cudaGetSymbolAddress((void**)&wqtl, g_wqt_l);
    cudaGetSymbolAddress((void**)&wkth, g_wkt_h);
    cudaGetSymbolAddress((void**)&wktl, g_wkt_l);
    cudaGetSymbolAddress((void**)&wvth, g_wvt_h);
    cudaGetSymbolAddress((void**)&wvtl, g_wvt_l);
    cudaGetSymbolAddress((void**)&woth, g_wot_h);
    cudaGetSymbolAddress((void**)&wotl, g_wot_l);

    static bool attr_done = false;
    if (!attr_done) {
        cudaFuncSetAttribute(attn_mma_kernel,
                             cudaFuncAttributeMaxDynamicSharedMemorySize, ASM_TOT);
        attr_done = true;
    }

    // Prep
    xconv_kernel<<<4096, 256>>>(x);
    wconv_kernel<<<dim3(32, 32), 256>>>(wq, wqth, wqtl, 1024);
    wconv_kernel<<<dim3(8, 32),  256>>>(wk, wkth, wktl, 256);
    wconv_kernel<<<dim3(8, 32),  256>>>(wv, wvth, wvtl, 256);
    wconv_kernel<<<dim3(32, 32), 256>>>(wo, woth, wotl, 1024);

    // QKV projection (HMMA split-bf16; Q/K -> bf16 hi/lo with RoPE; V -> fp32)
    qkv_hmma_kernel<<<dim3(12, 32), 256>>>(fc, fs);
    // V transpose + split
    vtrans_kernel<<<dim3(64, 2, 8), 256>>>();
    // Tensor-core flash attention
    attn_mma_kernel<<<dim3(16, 16, 2), 128, ASM_TOT>>>();
    // Output projection -> d_out
    oproj_hmma_kernel<<<dim3(8, 32), 256>>>(out);
}

// round 6
// speedup vs baseline: 8.3868x; 2.3129x over previous
#include <cuda_runtime.h>
#include <cuda_fp16.h>
#include <cstddef>
#include <cstdint>

#define SEQ    2048
#define KDIM   1024

// ---------------------------------------------------------------------------
// Device scratch (no allocation allowed)
// ---------------------------------------------------------------------------
__device__ __half g_xh[4096 * 1024];                 // x fp16
__device__ __half g_wqt[1024 * 1024];                // W^T [N,K] fp16
__device__ __half g_wkt[256 * 1024];
__device__ __half g_wvt[256 * 1024];
__device__ __half g_wot[1024 * 1024];
__device__ __half g_qh[4096 * 1024];                 // Q RoPE'd, ×0.125
__device__ __half g_kh[4096 * 256];                  // K RoPE'd
__device__ __half g_vth[8 * 64 * 2048];              // V^T [(b*4+hk)][d][s]
__device__ __half g_oh[4096 * 1024];                 // attention out

// ---------------------------------------------------------------------------
// PTX helpers (architecture-generic; plain sm_103 target)
// ---------------------------------------------------------------------------
__device__ __forceinline__ void ldsm_x4(uint32_t r[4], uint32_t addr) {
    asm volatile("ldmatrix.sync.aligned.m8n8.x4.shared.b16 {%0,%1,%2,%3}, [%4];"
        : "=r"(r[0]), "=r"(r[1]), "=r"(r[2]), "=r"(r[3]) : "r"(addr));
}
__device__ __forceinline__ void mma16816(float c[4], const uint32_t a[4], const uint32_t b[2]) {
    asm volatile(
        "mma.sync.aligned.m16n8k16.row.col.f32.f16.f16.f32 "
        "{%0,%1,%2,%3}, {%4,%5,%6,%7}, {%8,%9}, {%0,%1,%2,%3};"
        : "+f"(c[0]), "+f"(c[1]), "+f"(c[2]), "+f"(c[3])
        : "r"(a[0]), "r"(a[1]), "r"(a[2]), "r"(a[3]), "r"(b[0]), "r"(b[1]));
}
__device__ __forceinline__ void cp16(uint32_t dst, const void* src) {
    asm volatile("cp.async.cg.shared.global [%0], [%1], 16;" :: "r"(dst), "l"(src));
}
__device__ __forceinline__ uint32_t pack_f16(float lo, float hi) {
    const __half2 h = __floats2half2_rn(lo, hi);
    return *reinterpret_cast<const uint32_t*>(&h);
}

// ---------------------------------------------------------------------------
// fp16 HMMA GEMM: C[M,N] = A[M,1024] @ B[N,1024]^T.
// OMODE: 0 fp32 out | 1 RoPE -> fp16 | 2 RoPE+0.125 -> fp16 | 3 V-transpose fp16
// CTA 128x128, 8 warps (warp 64x32), K-chunk 32, cp.async double buffer.
// ---------------------------------------------------------------------------
template <int OMODE>
__device__ __forceinline__ void gemm_hmma(
    const __half* __restrict__ A, const __half* __restrict__ B,
    float* __restrict__ Cf, __half* __restrict__ Ch,
    int N, int brow, int bcol,
    const float* __restrict__ fc, const float* __restrict__ fs)
{
    // [stage][A/B][128 rows][32 halves = 64B]
    __shared__ char sm[2][2][8192];
    const uint32_t sb = (uint32_t)__cvta_generic_to_shared(&sm[0][0][0]);

    const int tid  = threadIdx.x;
    const int wid  = tid >> 5;
    const int lane = tid & 31;
    const int m_base = (wid >> 2) * 64;
    const int n_base = (wid & 3) * 32;

    const int lrow = tid >> 1;
    const __half* Asrc = A + (size_t)(brow + lrow) * KDIM;
    const __half* Bsrc = B + (size_t)(bcol + lrow) * KDIM;

    float acc[4][4][4];
    #pragma unroll
    for (int mi = 0; mi < 4; ++mi)
        #pragma unroll
        for (int nj = 0; nj < 4; ++nj)
            #pragma unroll
            for (int e = 0; e < 4; ++e) acc[mi][nj][e] = 0.f;

    const int arow0 = (lane & 15);
    const int akoff = (lane >> 4);
    const int brw   = ((lane >> 4) << 3) + (lane & 7);
    const int bkoff = ((lane >> 3) & 1);

    auto load_chunk = [&](int st, int c) {
        const uint32_t stoff = (uint32_t)(st * 16384);
        #pragma unroll
        for (int j = 0; j < 2; ++j) {
            const int cc = (tid & 1) * 2 + j;
            const uint32_t sw = (uint32_t)(((cc ^ ((lrow >> 1) & 3)) << 4) + (lrow << 6));
            cp16(sb + stoff +        sw, Asrc + c * 32 + cc * 8);
            cp16(sb + stoff + 8192 + sw, Bsrc + c * 32 + cc * 8);
        }
        asm volatile("cp.async.commit_group;");
    };

    const int NCH = KDIM / 32;   // 32
    load_chunk(0, 0);

    #pragma unroll 1
    for (int c = 0; c < NCH; ++c) {
        const int cur = c & 1;
        if (c + 1 < NCH) {
            load_chunk(cur ^ 1, c + 1);
            asm volatile("cp.async.wait_group 1;");
        } else {
            asm volatile("cp.async.wait_group 0;");
        }
        __syncthreads();
        const uint32_t stoff = sb + (uint32_t)(cur * 16384);

        #pragma unroll
        for (int kc = 0; kc < 2; ++kc) {
            uint32_t bf[4][2];
            #pragma unroll
            for (int g = 0; g < 2; ++g) {
                const int r = n_base + g * 16 + brw;
                const uint32_t ch = (uint32_t)((((2 * kc + bkoff) ^ ((r >> 1) & 3)) << 4) +
                                               (r << 6));
                uint32_t t4[4];
                ldsm_x4(t4, stoff + 8192 + ch);
                bf[g * 2][0] = t4[0]; bf[g * 2][1] = t4[1];
                bf[g * 2 + 1][0] = t4[2]; bf[g * 2 + 1][1] = t4[3];
            }
            #pragma unroll
            for (int mi = 0; mi < 4; ++mi) {
                const int r = m_base + mi * 16 + arow0;
                const uint32_t ch = (uint32_t)((((2 * kc + akoff) ^ ((r >> 1) & 3)) << 4) +
                                               (r << 6));
                uint32_t af[4];
                ldsm_x4(af, stoff + ch);
                #pragma unroll
                for (int nj = 0; nj < 4; ++nj)
                    mma16816(acc[mi][nj], af, bf[nj]);
            }
        }
        __syncthreads();
    }

    const int rbase = brow + m_base + (lane >> 2);
    const int cbase = bcol + n_base + (lane & 3) * 2;
    #pragma unroll
    for (int mi = 0; mi < 4; ++mi) {
        #pragma unroll
        for (int half = 0; half < 2; ++half) {
            const int r = rbase + mi * 16 + half * 8;
            const int srow = r & (SEQ - 1);
            #pragma unroll
            for (int nj = 0; nj < 4; ++nj) {
                const int col = cbase + nj * 8;
                float v0 = acc[mi][nj][half * 2];
                float v1 = acc[mi][nj][half * 2 + 1];
                if (OMODE == 1 || OMODE == 2) {
                    const int pair = (col & 63) >> 1;
                    const float cc = fc[srow * 32 + pair];
                    const float ss = fs[srow * 32 + pair];
                    float orv = v0 * cc - v1 * ss;
                    float oiv = v0 * ss + v1 * cc;
                    if (OMODE == 2) { orv *= 0.125f; oiv *= 0.125f; }
                    const __half2 hv = __floats2half2_rn(orv, oiv);
                    *reinterpret_cast<__half2*>(Ch + (size_t)r * N + col) = hv;
                } else if (OMODE == 3) {
                    // V^T: dst[(b*4+hk)*64 + d][s]
                    const int b  = r >> 11;
                    const int s  = r & (SEQ - 1);
                    const int hk = col >> 6;
                    const int d  = col & 63;
                    __half* dst = Ch + ((size_t)((b * 4 + hk) * 64 + d)) * SEQ + s;
                    dst[0]   = __float2half(v0);
                    dst[SEQ] = __float2half(v1);
                } else {
                    *reinterpret_cast<float2*>(Cf + (size_t)r * N + col) = make_float2(v0, v1);
                }
            }
        }
    }
}

__global__ void __launch_bounds__(256) qkv_hmma_kernel(
    const float* __restrict__ fc, const float* __restrict__ fs)
{
    const int bx   = blockIdx.x;
    const int brow = blockIdx.y * 128;
    if (bx < 8)
        gemm_hmma<2>(g_xh, g_wqt, nullptr, g_qh, 1024, brow, bx * 128, fc, fs);
    else if (bx < 10)
        gemm_hmma<1>(g_xh, g_wkt, nullptr, g_kh, 256, brow, (bx - 8) * 128, fc, fs);
    else
        gemm_hmma<3>(g_xh, g_wvt, nullptr, g_vth, 256, brow, (bx - 10) * 128, nullptr, nullptr);
}

__global__ void __launch_bounds__(256) oproj_hmma_kernel(float* __restrict__ out)
{
    gemm_hmma<0>(g_oh, g_wot, out, nullptr, 1024,
                 blockIdx.y * 128, blockIdx.x * 128, nullptr, nullptr);
}

// ---------------------------------------------------------------------------
// Prep kernels
// ---------------------------------------------------------------------------
__global__ void __launch_bounds__(256) xconv_kernel(const float* __restrict__ x)
{
    const int i = blockIdx.x * 256 + threadIdx.x;   // over 1M float4s
    const float4 v = reinterpret_cast<const float4*>(x)[i];
    uint2 st;
    st.x = pack_f16(v.x, v.y);
    st.y = pack_f16(v.z, v.w);
    reinterpret_cast<uint2*>(g_xh)[i] = st;
}

__global__ void __launch_bounds__(256) wconv_kernel(
    const float* __restrict__ W, __half* __restrict__ T, int N)
{
    __shared__ float t[32][33];
    const int n0 = blockIdx.x * 32, k0 = blockIdx.y * 32;
    const int tx = threadIdx.x & 31, ty = threadIdx.x >> 5;
    #pragma unroll
    for (int i = 0; i < 32; i += 8)
        t[ty + i][tx] = W[(size_t)(k0 + ty + i) * N + n0 + tx];
    __syncthreads();
    #pragma unroll
    for (int i = 0; i < 32; i += 8)
        T[(size_t)(n0 + ty + i) * 1024 + k0 + tx] = __float2half(t[tx][ty + i]);
}

// ---------------------------------------------------------------------------
// Tensor-core flash attention (fp16 single-pass). CTA = 128 queries x (b,h).
// 4 warps x 32 query rows. K-tiles of 64 keys, double-buffered cp.async.
// smem: Q 16K | stage{0,1}: K 8K + V^T 8K   (48 KB total)
// ---------------------------------------------------------------------------
#define ASM_Q   0
#define ASM_ST  16384
#define ASM_TOT 49152

__global__ void __launch_bounds__(128, 2) attn_mma_kernel()
{
    extern __shared__ char asmem[];
    const uint32_t sb = (uint32_t)__cvta_generic_to_shared(asmem);
    const int tid = threadIdx.x, w = tid >> 5, lane = tid & 31;
    const int b = blockIdx.z, h = blockIdx.y;
    const int qt = (int)gridDim.x - 1 - blockIdx.x;   // heavy tiles first
    const int hk = h >> 2;
    const int q0 = qt * 128;
    const int ntiles = 2 * qt + 2;

    // --- Q tile load (once): 128 rows x 64 d ---
    {
        const size_t qoff = (size_t)(b * SEQ + q0 + tid) * 1024 + h * 64;
        #pragma unroll
        for (int c = 0; c < 8; ++c) {
            const uint32_t sw = (uint32_t)((c ^ (tid & 7)) << 4) + (uint32_t)(tid << 7);
            cp16(sb + ASM_Q + sw, g_qh + qoff + c * 8);
        }
        asm volatile("cp.async.commit_group;");
    }
    // --- stage loader: K tile (64 keys x 64 d) + V^T tile (64 d x 64 s) ---
    auto load_stage = [&](int st, int kt) {
        const int row = tid >> 1;
        const int cb  = (tid & 1) * 4;
        const uint32_t so = sb + ASM_ST + (uint32_t)st * 16384;
        const size_t koff = (size_t)(b * SEQ + kt * 64 + row) * 256 + hk * 64;
        const size_t voff = (size_t)((b * 4 + hk) * 64 + row) * SEQ + kt * 64;
        #pragma unroll
        for (int i = 0; i < 4; ++i) {
            const int c = cb + i;
            const uint32_t sw = (uint32_t)((c ^ (row & 7)) << 4) + (uint32_t)(row << 7);
            cp16(so +        sw, g_kh + koff + c * 8);
            cp16(so + 8192 + sw, g_vth + voff + c * 8);
        }
        asm volatile("cp.async.commit_group;");
    };
    load_stage(0, 0);

    const int arow = lane & 15, akoff = lane >> 4;
    const int brw  = ((lane >> 4) << 3) + (lane & 7);
    const int bkoff = (lane >> 3) & 1;

    // --- hoist Q fragments (Q smem never overwritten) ---
    asm volatile("cp.async.wait_group 1;");
    __syncthreads();
    uint32_t qf[4][2][4];
    #pragma unroll
    for (int kc = 0; kc < 4; ++kc)
        #pragma unroll
        for (int mi = 0; mi < 2; ++mi) {
            const int r = w * 32 + mi * 16 + arow;
            const uint32_t ch = (uint32_t)(((2 * kc + akoff) ^ (r & 7)) << 4) +
                                (uint32_t)(r << 7);
            ldsm_x4(qf[kc][mi], sb + ASM_Q + ch);
        }

    float o[2][8][4];
    #pragma unroll
    for (int mi = 0; mi < 2; ++mi)
        #pragma unroll
        for (int nj = 0; nj < 8; ++nj)
            #pragma unroll
            for (int e = 0; e < 4; ++e) o[mi][nj][e] = 0.f;
    float mrow[4] = {-1e30f, -1e30f, -1e30f, -1e30f};
    float lrow[4] = {0.f, 0.f, 0.f, 0.f};

    #pragma unroll 1
    for (int kt = 0; kt < ntiles; ++kt) {
        const int st = kt & 1;
        if (kt + 1 < ntiles) {
            load_stage(st ^ 1, kt + 1);
            asm volatile("cp.async.wait_group 1;");
        } else {
            asm volatile("cp.async.wait_group 0;");
        }
        __syncthreads();
        const uint32_t so = sb + ASM_ST + (uint32_t)st * 16384;

        // ---- S = Q @ K^T ----
        float sc[2][8][4];
        #pragma unroll
        for (int mi = 0; mi < 2; ++mi)
            #pragma unroll
            for (int nj = 0; nj < 8; ++nj)
                #pragma unroll
                for (int e = 0; e < 4; ++e) sc[mi][nj][e] = 0.f;

        #pragma unroll
        for (int kc = 0; kc < 4; ++kc) {
            uint32_t kb[8][2];
            #pragma unroll
            for (int g = 0; g < 4; ++g) {
                const int r = g * 16 + brw;
                const uint32_t ch = (uint32_t)(((2 * kc + bkoff) ^ (r & 7)) << 4) +
                                    (uint32_t)(r << 7);
                uint32_t t4[4];
                ldsm_x4(t4, so + ch);
                kb[g * 2][0] = t4[0]; kb[g * 2][1] = t4[1];
                kb[g * 2 + 1][0] = t4[2]; kb[g * 2 + 1][1] = t4[3];
            }
            #pragma unroll
            for (int mi = 0; mi < 2; ++mi)
                #pragma unroll
                for (int nj = 0; nj < 8; ++nj)
                    mma16816(sc[mi][nj], qf[kc][mi], kb[nj]);
        }

        // ---- causal mask (partial tiles only) ----
        const int qwbase = q0 + w * 32;
        if (kt * 64 + 63 > qwbase) {
            const int jb = kt * 64 + (lane & 3) * 2;
            const int qb = qwbase + (lane >> 2);
            #pragma unroll
            for (int mi = 0; mi < 2; ++mi)
                #pragma unroll
                for (int nj = 0; nj < 8; ++nj)
                    #pragma unroll
                    for (int e = 0; e < 4; ++e) {
                        const int j = jb + nj * 8 + (e & 1);
                        const int q = qb + mi * 16 + ((e >> 1) << 3);
                        if (j > q) sc[mi][nj][e] = -1e30f;
                    }
        }

        // ---- online softmax ----
        float tm[4] = {-1e30f, -1e30f, -1e30f, -1e30f};
        #pragma unroll
        for (int mi = 0; mi < 2; ++mi)
            #pragma unroll
            for (int nj = 0; nj < 8; ++nj)
                #pragma unroll
                for (int e = 0; e < 4; ++e) {
                    const int ri = mi * 2 + (e >> 1);
                    tm[ri] = fmaxf(tm[ri], sc[mi][nj][e]);
                }
        float alpha[4];
        #pragma unroll
        for (int ri = 0; ri < 4; ++ri) {
            tm[ri] = fmaxf(tm[ri], __shfl_xor_sync(0xffffffffu, tm[ri], 1));
            tm[ri] = fmaxf(tm[ri], __shfl_xor_sync(0xffffffffu, tm[ri], 2));
            const float nm = fmaxf(mrow[ri], tm[ri]);
            alpha[ri] = __expf(mrow[ri] - nm);
            mrow[ri] = nm;
            lrow[ri] *= alpha[ri];
        }
        #pragma unroll
        for (int mi = 0; mi < 2; ++mi)
            #pragma unroll
            for (int nj = 0; nj < 8; ++nj) {
                o[mi][nj][0] *= alpha[mi * 2];     o[mi][nj][1] *= alpha[mi * 2];
                o[mi][nj][2] *= alpha[mi * 2 + 1]; o[mi][nj][3] *= alpha[mi * 2 + 1];
            }
        #pragma unroll
        for (int mi = 0; mi < 2; ++mi)
            #pragma unroll
            for (int nj = 0; nj < 8; ++nj)
                #pragma unroll
                for (int e = 0; e < 4; ++e) {
                    const int ri = mi * 2 + (e >> 1);
                    const float p = __expf(sc[mi][nj][e] - mrow[ri]);
                    sc[mi][nj][e] = p;
                    lrow[ri] += p;
                }

        // ---- O += P @ V ----
        #pragma unroll
        for (int kc = 0; kc < 4; ++kc) {
            uint32_t ap[2][4];
            #pragma unroll
            for (int mi = 0; mi < 2; ++mi) {
                const float* s0 = sc[mi][2 * kc];
                const float* s1 = sc[mi][2 * kc + 1];
                ap[mi][0] = pack_f16(s0[0], s0[1]);
                ap[mi][1] = pack_f16(s0[2], s0[3]);
                ap[mi][2] = pack_f16(s1[0], s1[1]);
                ap[mi][3] = pack_f16(s1[2], s1[3]);
            }
            uint32_t vb[8][2];
            #pragma unroll
            for (int g = 0; g < 4; ++g) {
                const int r = g * 16 + brw;
                const uint32_t ch = (uint32_t)(((2 * kc + bkoff) ^ (r & 7)) << 4) +
                                    (uint32_t)(r << 7);
                uint32_t t4[4];
                ldsm_x4(t4, so + 8192 + ch);
                vb[g * 2][0] = t4[0]; vb[g * 2][1] = t4[1];
                vb[g * 2 + 1][0] = t4[2]; vb[g * 2 + 1][1] = t4[3];
            }
            #pragma unroll
            for (int mi = 0; mi < 2; ++mi)
                #pragma unroll
                for (int nj = 0; nj < 8; ++nj)
                    mma16816(o[mi][nj], ap[mi], vb[nj]);
        }
        __syncthreads();
    }

    // ---- epilogue: normalize + write fp16 ----
    float linv[4];
    #pragma unroll
    for (int ri = 0; ri < 4; ++ri) {
        float l = lrow[ri];
        l += __shfl_xor_sync(0xffffffffu, l, 1);
        l += __shfl_xor_sync(0xffffffffu, l, 2);
        linv[ri] = 1.0f / l;
    }
    #pragma unroll
    for (int mi = 0; mi < 2; ++mi) {
        #pragma unroll
        for (int half = 0; half < 2; ++half) {
            const int rloc = w * 32 + mi * 16 + (lane >> 2) + half * 8;
            const size_t rg = (size_t)(b * SEQ + q0 + rloc) * 1024 + h * 64;
            const float inv = linv[mi * 2 + half];
            #pragma unroll
            for (int nj = 0; nj < 8; ++nj) {
                const int col = nj * 8 + (lane & 3) * 2;
                const __half2 hv = __floats2half2_rn(o[mi][nj][half * 2] * inv,
                                                     o[mi][nj][half * 2 + 1] * inv);
                *reinterpret_cast<__half2*>(g_oh + rg + col) = hv;
            }
        }
    }
}

// ---------------------------------------------------------------------------
// Inputs: x, start_pos, freqs_cos, freqs_sin, mask, wq, wk, wv, wo
// ---------------------------------------------------------------------------
extern "C" void kernel_launch(void* const* d_in, const int* in_sizes, int n_in,
                              void* d_out, int out_size)
{
    const float* x  = (const float*)d_in[0];
    const float* fc = (const float*)d_in[2];
    const float* fs = (const float*)d_in[3];
    const float* wq = (const float*)d_in[5];
    const float* wk = (const float*)d_in[6];
    const float* wv = (const float*)d_in[7];
    const float* wo = (const float*)d_in[8];
    float* out = (float*)d_out;

    __half *wqt, *wkt, *wvt, *wot;
    cudaGetSymbolAddress((void**)&wqt, g_wqt);
    cudaGetSymbolAddress((void**)&wkt, g_wkt);
    cudaGetSymbolAddress((void**)&wvt, g_wvt);
    cudaGetSymbolAddress((void**)&wot, g_wot);

    // Prep: fp32 -> fp16 (x) and transposed fp16 weights
    xconv_kernel<<<4096, 256>>>(x);
    wconv_kernel<<<dim3(32, 32), 256>>>(wq, wqt, 1024);
    wconv_kernel<<<dim3(8, 32),  256>>>(wk, wkt, 256);
    wconv_kernel<<<dim3(8, 32),  256>>>(wv, wvt, 256);
    wconv_kernel<<<dim3(32, 32), 256>>>(wo, wot, 1024);

    // QKV projection (fp16 HMMA; Q/K RoPE'd fp16; V written transposed fp16)
    qkv_hmma_kernel<<<dim3(12, 32), 256>>>(fc, fs);
    // Tensor-core flash attention
    attn_mma_kernel<<<dim3(16, 16, 2), 128, ASM_TOT>>>();
    // Output projection -> d_out (fp32)
    oproj_hmma_kernel<<<dim3(8, 32), 256>>>(out);
}